// round 1
// baseline (speedup 1.0000x reference)
#include <cuda_runtime.h>
#include <cuda_bf16.h>

#define LNUM 6
#define HNUM 12
#define DDIM 768
#define DHD  64
#define FDIM 3072
#define VOC  32000
#define SEQ  1024
#define BAT  2
#define TTOK (BAT*SEQ)
#define EPS  1e-5f

// ---------------- scratch (static device globals; no allocation) ----------------
__device__ float g_x [TTOK*DDIM];
__device__ float g_xn[TTOK*DDIM];
__device__ float g_q [TTOK*DDIM];
__device__ float g_k [TTOK*DDIM];
__device__ float g_v [TTOK*DDIM];
__device__ float g_ao[TTOK*DDIM];
__device__ float g_h1[TTOK*FDIM];
__device__ float g_sc[(long long)BAT*HNUM*SEQ*SEQ];

// ---------------- embedding ----------------
__global__ void embed_k(const int* __restrict__ X, const float* __restrict__ emb,
                        const float* __restrict__ pos, float* __restrict__ x)
{
    int t = blockIdx.x;
    int tok = X[t];
    int s = t % SEQ;
    const float* er = emb + (long long)tok * DDIM;
    const float* pr = pos + (long long)s * DDIM;
    float* xr = x + (long long)t * DDIM;
    for (int d = threadIdx.x; d < DDIM; d += blockDim.x)
        xr[d] = er[d] + pr[d];
}

// ---------------- layernorm (one block per row) ----------------
__device__ __forceinline__ float warp_sum(float v) {
    #pragma unroll
    for (int o = 16; o; o >>= 1) v += __shfl_xor_sync(0xffffffffu, v, o);
    return v;
}

__global__ void ln_k(const float* __restrict__ x, const float* __restrict__ g,
                     const float* __restrict__ b, float* __restrict__ y)
{
    int row = blockIdx.x;
    const float* xr = x + (long long)row * DDIM;
    float* yr = y + (long long)row * DDIM;
    int tid = threadIdx.x;

    float sum = 0.f, sq = 0.f;
    for (int i = tid; i < DDIM; i += 256) {
        float v = xr[i];
        sum += v; sq += v * v;
    }
    __shared__ float shs[8], shq[8];
    float s1 = warp_sum(sum), s2 = warp_sum(sq);
    int wid = tid >> 5, lane = tid & 31;
    if (lane == 0) { shs[wid] = s1; shq[wid] = s2; }
    __syncthreads();
    float ts = 0.f, tq = 0.f;
    #pragma unroll
    for (int w = 0; w < 8; w++) { ts += shs[w]; tq += shq[w]; }
    float mu = ts * (1.0f / DDIM);
    float var = tq * (1.0f / DDIM) - mu * mu;
    float r = rsqrtf(var + EPS);
    for (int i = tid; i < DDIM; i += 256)
        yr[i] = (xr[i] - mu) * r * g[i] + b[i];
}

// ---------------- causal softmax (scale folded in), one block per row ----------------
__global__ void softmax_k(float* __restrict__ sc, float scale)
{
    long long row = blockIdx.x;              // 0 .. B*H*S-1
    int s = (int)(row % SEQ);
    float* p = sc + row * (long long)SEQ;
    int n = s + 1;
    int tid = threadIdx.x;

    float mx = -1e30f;
    for (int i = tid; i < n; i += 256) mx = fmaxf(mx, p[i] * scale);
    __shared__ float sh[8];
    #pragma unroll
    for (int o = 16; o; o >>= 1) mx = fmaxf(mx, __shfl_xor_sync(0xffffffffu, mx, o));
    int wid = tid >> 5, lane = tid & 31;
    if (lane == 0) sh[wid] = mx;
    __syncthreads();
    float gmx = -1e30f;
    #pragma unroll
    for (int w = 0; w < 8; w++) gmx = fmaxf(gmx, sh[w]);

    float sum = 0.f;
    for (int i = tid; i < n; i += 256) {
        float e = expf(p[i] * scale - gmx);
        p[i] = e;
        sum += e;
    }
    float s1 = warp_sum(sum);
    __syncthreads();
    if (lane == 0) sh[wid] = s1;
    __syncthreads();
    float tot = 0.f;
    #pragma unroll
    for (int w = 0; w < 8; w++) tot += sh[w];
    float inv = 1.0f / tot;
    for (int i = tid; i < n; i += 256) p[i] *= inv;
    for (int i = n + tid; i < SEQ; i += 256) p[i] = 0.f;
}

// ---------------- generic batched SGEMM ----------------
// C[m,n] = sum_k A[m,k] * B[k,n]  (+bias[n]) (+C_old) (relu)
// TRANSB: B element (k,n) at B[n*ldb + k]
// batch z decomposed as (bz = z/nH, hz = z%nH); pointer offsets bz*s?b + hz*s?h.
template<int BM, int BN, int BK, int TM, int TN, bool TRANSB, bool RELU, bool RESID>
__global__ void __launch_bounds__(256) gemm_k(
    const float* __restrict__ Ag, const float* __restrict__ Bg,
    const float* __restrict__ biasg, float* __restrict__ Cg,
    int M, int N, int K, int lda, int ldb, int ldc,
    int nH, long long sAb, long long sAh, long long sBb, long long sBh,
    long long sCb, long long sCh, long long sbias)
{
    constexpr int NTH = 256;
    static_assert((BM / TM) * (BN / TN) == NTH, "thread layout");

    const int z = blockIdx.z;
    const int bz = z / nH, hz = z % nH;
    const float* A = Ag + bz * sAb + hz * sAh;
    const float* B = Bg + bz * sBb + hz * sBh;
    float* C = Cg + bz * sCb + hz * sCh;
    const float* bias = biasg ? (biasg + hz * sbias) : nullptr;

    __shared__ __align__(16) float As[BK][BM];
    __shared__ __align__(16) float Bs[BK][BN];

    const int tid = threadIdx.x;
    const int tx = tid % (BN / TN);
    const int ty = tid / (BN / TN);
    const int m0 = blockIdx.y * BM;
    const int n0 = blockIdx.x * BN;

    float acc[TM][TN];
    #pragma unroll
    for (int i = 0; i < TM; i++)
        #pragma unroll
        for (int j = 0; j < TN; j++) acc[i][j] = 0.f;

    for (int k0 = 0; k0 < K; k0 += BK) {
        constexpr int AIT = BM * BK / 4 / NTH;
        #pragma unroll
        for (int it = 0; it < AIT; it++) {
            int vv = tid + it * NTH;
            int row = vv / (BK / 4);
            int cv  = vv % (BK / 4);
            const float4 a4 = *reinterpret_cast<const float4*>(
                &A[(long long)(m0 + row) * lda + k0 + cv * 4]);
            As[cv * 4 + 0][row] = a4.x;
            As[cv * 4 + 1][row] = a4.y;
            As[cv * 4 + 2][row] = a4.z;
            As[cv * 4 + 3][row] = a4.w;
        }
        constexpr int BIT = BK * BN / 4 / NTH;
        if (!TRANSB) {
            #pragma unroll
            for (int it = 0; it < BIT; it++) {
                int vv = tid + it * NTH;
                int row = vv / (BN / 4);      // k
                int cv  = vv % (BN / 4);
                *reinterpret_cast<float4*>(&Bs[row][cv * 4]) =
                    *reinterpret_cast<const float4*>(
                        &B[(long long)(k0 + row) * ldb + n0 + cv * 4]);
            }
        } else {
            #pragma unroll
            for (int it = 0; it < BIT; it++) {
                int vv = tid + it * NTH;
                int nn = vv / (BK / 4);       // n
                int cv = vv % (BK / 4);
                const float4 b4 = *reinterpret_cast<const float4*>(
                    &B[(long long)(n0 + nn) * ldb + k0 + cv * 4]);
                Bs[cv * 4 + 0][nn] = b4.x;
                Bs[cv * 4 + 1][nn] = b4.y;
                Bs[cv * 4 + 2][nn] = b4.z;
                Bs[cv * 4 + 3][nn] = b4.w;
            }
        }
        __syncthreads();
        #pragma unroll
        for (int k = 0; k < BK; k++) {
            float ar[TM], br[TN];
            #pragma unroll
            for (int i = 0; i < TM; i += 4)
                *reinterpret_cast<float4*>(&ar[i]) =
                    *reinterpret_cast<const float4*>(&As[k][ty * TM + i]);
            #pragma unroll
            for (int j = 0; j < TN; j += 4)
                *reinterpret_cast<float4*>(&br[j]) =
                    *reinterpret_cast<const float4*>(&Bs[k][tx * TN + j]);
            #pragma unroll
            for (int i = 0; i < TM; i++)
                #pragma unroll
                for (int j = 0; j < TN; j++)
                    acc[i][j] = fmaf(ar[i], br[j], acc[i][j]);
        }
        __syncthreads();
    }

    #pragma unroll
    for (int i = 0; i < TM; i++) {
        int m = m0 + ty * TM + i;
        #pragma unroll
        for (int j = 0; j < TN; j++) {
            int n = n0 + tx * TN + j;
            long long idx = (long long)m * ldc + n;
            float v = acc[i][j];
            if (bias) v += bias[n];
            if (RESID) v += C[idx];
            if (RELU) v = fmaxf(v, 0.f);
            C[idx] = v;
        }
    }
}

// ---------------- host launchers ----------------
template<bool TRANSB, bool RELU, bool RESID>
static void gemm_big(const float* A, const float* B, const float* bias, float* C,
                     int M, int N, int K, int lda, int ldb, int ldc,
                     int Z = 1, int nH = 1,
                     long long sAb = 0, long long sAh = 0,
                     long long sBb = 0, long long sBh = 0,
                     long long sCb = 0, long long sCh = 0, long long sbias = 0)
{
    dim3 grid(N / 128, M / 128, Z);
    gemm_k<128, 128, 16, 8, 8, TRANSB, RELU, RESID><<<grid, 256>>>(
        A, B, bias, C, M, N, K, lda, ldb, ldc, nH, sAb, sAh, sBb, sBh, sCb, sCh, sbias);
}

template<bool TRANSB, bool RELU, bool RESID>
static void gemm_small(const float* A, const float* B, const float* bias, float* C,
                       int M, int N, int K, int lda, int ldb, int ldc,
                       int Z = 1, int nH = 1,
                       long long sAb = 0, long long sAh = 0,
                       long long sBb = 0, long long sBh = 0,
                       long long sCb = 0, long long sCh = 0, long long sbias = 0)
{
    dim3 grid(N / 64, M / 64, Z);
    gemm_k<64, 64, 16, 4, 4, TRANSB, RELU, RESID><<<grid, 256>>>(
        A, B, bias, C, M, N, K, lda, ldb, ldc, nH, sAb, sAh, sBb, sBh, sCb, sCh, sbias);
}

extern "C" void kernel_launch(void* const* d_in, const int* in_sizes, int n_in,
                              void* d_out, int out_size)
{
    const int*   X      = (const int*)  d_in[0];
    const float* emb    = (const float*)d_in[1];
    const float* pos    = (const float*)d_in[2];
    const float* Wq     = (const float*)d_in[3];
    const float* bq     = (const float*)d_in[4];
    const float* Wk     = (const float*)d_in[5];
    const float* bk     = (const float*)d_in[6];
    const float* Wv     = (const float*)d_in[7];
    const float* bv     = (const float*)d_in[8];
    const float* Wo     = (const float*)d_in[9];
    const float* bo     = (const float*)d_in[10];
    const float* ln1s   = (const float*)d_in[11];
    const float* ln1b   = (const float*)d_in[12];
    const float* ln2s   = (const float*)d_in[13];
    const float* ln2b   = (const float*)d_in[14];
    const float* W1     = (const float*)d_in[15];
    const float* b1     = (const float*)d_in[16];
    const float* W2     = (const float*)d_in[17];
    const float* b2     = (const float*)d_in[18];
    const float* lnfs   = (const float*)d_in[19];
    const float* lnfb   = (const float*)d_in[20];
    const float* headb  = (const float*)d_in[21];
    float* out = (float*)d_out;

    float *x, *xn, *q, *k, *v, *ao, *h1, *sc;
    cudaGetSymbolAddress((void**)&x,  g_x);
    cudaGetSymbolAddress((void**)&xn, g_xn);
    cudaGetSymbolAddress((void**)&q,  g_q);
    cudaGetSymbolAddress((void**)&k,  g_k);
    cudaGetSymbolAddress((void**)&v,  g_v);
    cudaGetSymbolAddress((void**)&ao, g_ao);
    cudaGetSymbolAddress((void**)&h1, g_h1);
    cudaGetSymbolAddress((void**)&sc, g_sc);

    const long long sT = (long long)SEQ * DDIM;          // per-batch stride in [T,768] bufs
    const long long sSS = (long long)SEQ * SEQ;          // per-head stride in scores
    const float attn_scale = 0.125f;                     // 1/sqrt(64)

    // x = emb[X] + pos
    embed_k<<<TTOK, 256>>>(X, emb, pos, x);

    for (int l = 0; l < LNUM; l++) {
        const float* Wq_l = Wq + (long long)l * HNUM * DDIM * DHD;
        const float* Wk_l = Wk + (long long)l * HNUM * DDIM * DHD;
        const float* Wv_l = Wv + (long long)l * HNUM * DDIM * DHD;
        const float* bq_l = bq + (long long)l * HNUM * DHD;
        const float* bk_l = bk + (long long)l * HNUM * DHD;
        const float* bv_l = bv + (long long)l * HNUM * DHD;

        // xn = LN1(x)
        ln_k<<<TTOK, 256>>>(x, ln1s + l * DDIM, ln1b + l * DDIM, xn);

        // q/k/v: per-head GEMM [T,768] @ [768,64]; q layout [T, H*DH]
        gemm_small<false, false, false>(xn, Wq_l, bq_l, q, TTOK, DHD, DDIM, DDIM, DHD, DDIM,
                                        HNUM, HNUM, 0, 0, 0, (long long)DDIM * DHD, 0, DHD, DHD);
        gemm_small<false, false, false>(xn, Wk_l, bk_l, k, TTOK, DHD, DDIM, DDIM, DHD, DDIM,
                                        HNUM, HNUM, 0, 0, 0, (long long)DDIM * DHD, 0, DHD, DHD);
        gemm_small<false, false, false>(xn, Wv_l, bv_l, v, TTOK, DHD, DDIM, DDIM, DHD, DDIM,
                                        HNUM, HNUM, 0, 0, 0, (long long)DDIM * DHD, 0, DHD, DHD);

        // scores[b,h] = q[b,h] @ k[b,h]^T   (M=N=1024, K=64)
        gemm_big<true, false, false>(q, k, nullptr, sc, SEQ, SEQ, DHD, DDIM, DDIM, SEQ,
                                     BAT * HNUM, HNUM,
                                     sT, DHD, sT, DHD,
                                     (long long)HNUM * sSS, sSS, 0);

        // causal softmax with scale
        softmax_k<<<BAT * HNUM * SEQ, 256>>>(sc, attn_scale);

        // ao[b,h] = attn @ v[b,h]   (M=1024, N=64, K=1024), writes [T, H*DH] layout
        gemm_small<false, false, false>(sc, v, nullptr, ao, SEQ, DHD, SEQ, SEQ, DDIM, DDIM,
                                        BAT * HNUM, HNUM,
                                        (long long)HNUM * sSS, sSS,
                                        sT, DHD, sT, DHD, 0);

        // x += ao @ Wo + bo
        gemm_big<false, false, true>(ao, Wo + (long long)l * DDIM * DDIM, bo + l * DDIM, x,
                                     TTOK, DDIM, DDIM, DDIM, DDIM, DDIM);

        // xn = LN2(x)
        ln_k<<<TTOK, 256>>>(x, ln2s + l * DDIM, ln2b + l * DDIM, xn);

        // h1 = relu(xn @ W1 + b1)
        gemm_big<false, true, false>(xn, W1 + (long long)l * DDIM * FDIM, b1 + l * FDIM, h1,
                                     TTOK, FDIM, DDIM, DDIM, FDIM, FDIM);

        // x += h1 @ W2 + b2
        gemm_big<false, false, true>(h1, W2 + (long long)l * FDIM * DDIM, b2 + l * DDIM, x,
                                     TTOK, DDIM, FDIM, FDIM, DDIM, DDIM);
    }

    // xn = LNf(x)
    ln_k<<<TTOK, 256>>>(x, lnfs, lnfb, xn);

    // logits = xn @ emb^T + head_b   (M=2048, N=32000, K=768)
    gemm_big<true, false, false>(xn, emb, headb, out, TTOK, VOC, DDIM, DDIM, DDIM, VOC);
}

// round 2
// speedup vs baseline: 1.6389x; 1.6389x over previous
#include <cuda_runtime.h>
#include <cuda_bf16.h>
#include <mma.h>

using namespace nvcuda;

#define LNUM 6
#define HNUM 12
#define DDIM 768
#define DHD  64
#define FDIM 3072
#define VOC  32000
#define SEQ  1024
#define BAT  2
#define TTOK (BAT*SEQ)
#define EPS  1e-5f

// ---------------- scratch (static device globals; no allocation) ----------------
__device__ float g_x [TTOK*DDIM];
__device__ float g_xn[TTOK*DDIM];
__device__ float g_q [TTOK*DDIM];
__device__ float g_k [TTOK*DDIM];
__device__ float g_v [TTOK*DDIM];
__device__ float g_ao[TTOK*DDIM];
__device__ float g_h1[TTOK*FDIM];
__device__ float g_sc[(long long)BAT*HNUM*SEQ*SEQ];

// ---------------- embedding ----------------
__global__ void embed_k(const int* __restrict__ X, const float* __restrict__ emb,
                        const float* __restrict__ pos, float* __restrict__ x)
{
    int t = blockIdx.x;
    int tok = X[t];
    int s = t % SEQ;
    const float* er = emb + (long long)tok * DDIM;
    const float* pr = pos + (long long)s * DDIM;
    float* xr = x + (long long)t * DDIM;
    for (int d = threadIdx.x; d < DDIM; d += blockDim.x)
        xr[d] = er[d] + pr[d];
}

// ---------------- layernorm (one block per row) ----------------
__device__ __forceinline__ float warp_sum(float v) {
    #pragma unroll
    for (int o = 16; o; o >>= 1) v += __shfl_xor_sync(0xffffffffu, v, o);
    return v;
}

__global__ void ln_k(const float* __restrict__ x, const float* __restrict__ g,
                     const float* __restrict__ b, float* __restrict__ y)
{
    int row = blockIdx.x;
    const float* xr = x + (long long)row * DDIM;
    float* yr = y + (long long)row * DDIM;
    int tid = threadIdx.x;

    float sum = 0.f, sq = 0.f;
    for (int i = tid; i < DDIM; i += 256) {
        float v = xr[i];
        sum += v; sq += v * v;
    }
    __shared__ float shs[8], shq[8];
    float s1 = warp_sum(sum), s2 = warp_sum(sq);
    int wid = tid >> 5, lane = tid & 31;
    if (lane == 0) { shs[wid] = s1; shq[wid] = s2; }
    __syncthreads();
    float ts = 0.f, tq = 0.f;
    #pragma unroll
    for (int w = 0; w < 8; w++) { ts += shs[w]; tq += shq[w]; }
    float mu = ts * (1.0f / DDIM);
    float var = tq * (1.0f / DDIM) - mu * mu;
    float r = rsqrtf(var + EPS);
    for (int i = tid; i < DDIM; i += 256)
        yr[i] = (xr[i] - mu) * r * g[i] + b[i];
}

// ---------------- causal softmax (scale folded in), one block per row ----------------
__global__ void softmax_k(float* __restrict__ sc, float scale)
{
    long long row = blockIdx.x;              // 0 .. B*H*S-1
    int s = (int)(row % SEQ);
    float* p = sc + row * (long long)SEQ;
    int n = s + 1;
    int tid = threadIdx.x;

    float mx = -1e30f;
    for (int i = tid; i < n; i += 256) mx = fmaxf(mx, p[i] * scale);
    __shared__ float sh[8];
    #pragma unroll
    for (int o = 16; o; o >>= 1) mx = fmaxf(mx, __shfl_xor_sync(0xffffffffu, mx, o));
    int wid = tid >> 5, lane = tid & 31;
    if (lane == 0) sh[wid] = mx;
    __syncthreads();
    float gmx = -1e30f;
    #pragma unroll
    for (int w = 0; w < 8; w++) gmx = fmaxf(gmx, sh[w]);

    float sum = 0.f;
    for (int i = tid; i < n; i += 256) {
        float e = expf(p[i] * scale - gmx);
        p[i] = e;
        sum += e;
    }
    float s1 = warp_sum(sum);
    __syncthreads();
    if (lane == 0) sh[wid] = s1;
    __syncthreads();
    float tot = 0.f;
    #pragma unroll
    for (int w = 0; w < 8; w++) tot += sh[w];
    float inv = 1.0f / tot;
    for (int i = tid; i < n; i += 256) p[i] *= inv;
    for (int i = n + tid; i < SEQ; i += 256) p[i] = 0.f;
}

// ---------------- split helper: fp32 -> bf16 hi + bf16 lo ----------------
__device__ __forceinline__ void split2(float v, __nv_bfloat16& h, __nv_bfloat16& l)
{
    h = __float2bfloat16(v);
    l = __float2bfloat16(v - __bfloat162float(h));
}

// ---------------- tensor-core batched GEMM (3x bf16 split, fp32 accumulate) --------
// C[m,n] = sum_k A[m,k]*B[k,n] (+bias[n]) (+C_old) (relu)
// TRANSB: B element (k,n) at B[n*ldb + k]
// CSKIP: skip blocks fully above the causal diagonal (scores GEMM)
// CK:    limit K loop to k < m0+BM (attn-probs GEMM; P is zero above diagonal)
template<int BM, int BN, int BK, int WM, int WN,
         bool TRANSB, bool RELU, bool RESID, bool CSKIP, bool CK>
__global__ void __launch_bounds__(256) gemm_tc(
    const float* __restrict__ Ag, const float* __restrict__ Bg,
    const float* __restrict__ biasg, float* __restrict__ Cg,
    int M, int N, int K, int lda, int ldb, int ldc,
    int nH, long long sAb, long long sAh, long long sBb, long long sBh,
    long long sCb, long long sCh, long long sbias)
{
    constexpr int NWARP = (BM / WM) * (BN / WN);
    static_assert(NWARP == 8, "8 warps");
    constexpr int MI = WM / 16;
    constexpr int NI = WN / 16;
    constexpr int LDAS = BK + 8;
    constexpr int LDBS = BN + 8;

    const int m0 = blockIdx.y * BM;
    const int n0 = blockIdx.x * BN;
    if (CSKIP && n0 >= m0 + BM) return;   // fully masked (never read)

    const int z = blockIdx.z;
    const int bz = z / nH, hz = z % nH;
    const float* A = Ag + bz * sAb + hz * sAh;
    const float* B = Bg + bz * sBb + hz * sBh;
    float* C = Cg + bz * sCb + hz * sCh;
    const float* bias = biasg ? (biasg + hz * sbias) : nullptr;

    __shared__ __align__(16) __nv_bfloat16 As_hi[BM * LDAS];
    __shared__ __align__(16) __nv_bfloat16 As_lo[BM * LDAS];
    __shared__ __align__(16) __nv_bfloat16 Bs_hi[BK * LDBS];
    __shared__ __align__(16) __nv_bfloat16 Bs_lo[BK * LDBS];
    __shared__ __align__(16) float stage[NWARP][16 * 16];

    const int tid = threadIdx.x;
    const int w = tid >> 5;
    const int lane = tid & 31;
    const int warp_m = (w / (BN / WN)) * WM;
    const int warp_n = (w % (BN / WN)) * WN;

    wmma::fragment<wmma::accumulator, 16, 16, 16, float> acc[MI][NI];
    #pragma unroll
    for (int i = 0; i < MI; i++)
        #pragma unroll
        for (int j = 0; j < NI; j++) wmma::fill_fragment(acc[i][j], 0.f);

    const int Kend = CK ? (m0 + BM < K ? m0 + BM : K) : K;

    for (int k0 = 0; k0 < Kend; k0 += BK) {
        // ---- stage A tile (split fp32 -> hi/lo bf16) ----
        constexpr int AF4 = BM * BK / 4;
        #pragma unroll
        for (int it = 0; it < AF4 / 256; it++) {
            int vv = tid + it * 256;
            int row = vv / (BK / 4);
            int c4  = vv % (BK / 4);
            float4 a4 = *reinterpret_cast<const float4*>(
                &A[(long long)(m0 + row) * lda + k0 + c4 * 4]);
            int base = row * LDAS + c4 * 4;
            __nv_bfloat16 h, l;
            split2(a4.x, h, l); As_hi[base + 0] = h; As_lo[base + 0] = l;
            split2(a4.y, h, l); As_hi[base + 1] = h; As_lo[base + 1] = l;
            split2(a4.z, h, l); As_hi[base + 2] = h; As_lo[base + 2] = l;
            split2(a4.w, h, l); As_hi[base + 3] = h; As_lo[base + 3] = l;
        }
        // ---- stage B tile ----
        constexpr int BF4 = BK * BN / 4;
        if (!TRANSB) {
            #pragma unroll
            for (int it = 0; it < BF4 / 256; it++) {
                int vv = tid + it * 256;
                int row = vv / (BN / 4);      // k
                int c4  = vv % (BN / 4);
                float4 b4 = *reinterpret_cast<const float4*>(
                    &B[(long long)(k0 + row) * ldb + n0 + c4 * 4]);
                int base = row * LDBS + c4 * 4;
                __nv_bfloat16 h, l;
                split2(b4.x, h, l); Bs_hi[base + 0] = h; Bs_lo[base + 0] = l;
                split2(b4.y, h, l); Bs_hi[base + 1] = h; Bs_lo[base + 1] = l;
                split2(b4.z, h, l); Bs_hi[base + 2] = h; Bs_lo[base + 2] = l;
                split2(b4.w, h, l); Bs_hi[base + 3] = h; Bs_lo[base + 3] = l;
            }
        } else {
            #pragma unroll
            for (int it = 0; it < BF4 / 256; it++) {
                int vv = tid + it * 256;
                int nn = vv / (BK / 4);       // n
                int c4 = vv % (BK / 4);
                float4 b4 = *reinterpret_cast<const float4*>(
                    &B[(long long)(n0 + nn) * ldb + k0 + c4 * 4]);
                __nv_bfloat16 h, l;
                split2(b4.x, h, l); Bs_hi[(c4*4+0)*LDBS + nn] = h; Bs_lo[(c4*4+0)*LDBS + nn] = l;
                split2(b4.y, h, l); Bs_hi[(c4*4+1)*LDBS + nn] = h; Bs_lo[(c4*4+1)*LDBS + nn] = l;
                split2(b4.z, h, l); Bs_hi[(c4*4+2)*LDBS + nn] = h; Bs_lo[(c4*4+2)*LDBS + nn] = l;
                split2(b4.w, h, l); Bs_hi[(c4*4+3)*LDBS + nn] = h; Bs_lo[(c4*4+3)*LDBS + nn] = l;
            }
        }
        __syncthreads();

        // ---- MMAs ----
        #pragma unroll
        for (int kk = 0; kk < BK / 16; kk++) {
            wmma::fragment<wmma::matrix_a, 16, 16, 16, __nv_bfloat16, wmma::row_major> a_hi[MI], a_lo[MI];
            #pragma unroll
            for (int i = 0; i < MI; i++) {
                wmma::load_matrix_sync(a_hi[i], As_hi + (warp_m + i * 16) * LDAS + kk * 16, LDAS);
                wmma::load_matrix_sync(a_lo[i], As_lo + (warp_m + i * 16) * LDAS + kk * 16, LDAS);
            }
            #pragma unroll
            for (int j = 0; j < NI; j++) {
                wmma::fragment<wmma::matrix_b, 16, 16, 16, __nv_bfloat16, wmma::row_major> b_hi, b_lo;
                wmma::load_matrix_sync(b_hi, Bs_hi + (kk * 16) * LDBS + warp_n + j * 16, LDBS);
                wmma::load_matrix_sync(b_lo, Bs_lo + (kk * 16) * LDBS + warp_n + j * 16, LDBS);
                #pragma unroll
                for (int i = 0; i < MI; i++) {
                    wmma::mma_sync(acc[i][j], a_hi[i], b_hi, acc[i][j]);
                    wmma::mma_sync(acc[i][j], a_hi[i], b_lo, acc[i][j]);
                    wmma::mma_sync(acc[i][j], a_lo[i], b_hi, acc[i][j]);
                }
            }
        }
        __syncthreads();
    }

    // ---- epilogue via per-warp smem staging ----
    #pragma unroll
    for (int i = 0; i < MI; i++) {
        #pragma unroll
        for (int j = 0; j < NI; j++) {
            float* st = stage[w];
            wmma::store_matrix_sync(st, acc[i][j], 16, wmma::mem_row_major);
            __syncwarp();
            #pragma unroll
            for (int e = 0; e < 8; e++) {
                int idx = lane + 32 * e;
                int r = idx >> 4, c = idx & 15;
                int m = m0 + warp_m + i * 16 + r;
                int n = n0 + warp_n + j * 16 + c;
                long long cidx = (long long)m * ldc + n;
                float v = st[idx];
                if (bias) v += bias[n];
                if (RESID) v += C[cidx];
                if (RELU) v = fmaxf(v, 0.f);
                C[cidx] = v;
            }
            __syncwarp();
        }
    }
}

// ---------------- host launchers ----------------
template<bool TRANSB, bool RELU, bool RESID, bool CSKIP = false, bool CK = false>
static void gemm_big(const float* A, const float* B, const float* bias, float* C,
                     int M, int N, int K, int lda, int ldb, int ldc,
                     int Z = 1, int nH = 1,
                     long long sAb = 0, long long sAh = 0,
                     long long sBb = 0, long long sBh = 0,
                     long long sCb = 0, long long sCh = 0, long long sbias = 0)
{
    dim3 grid(N / 128, M / 128, Z);
    gemm_tc<128, 128, 32, 32, 64, TRANSB, RELU, RESID, CSKIP, CK><<<grid, 256>>>(
        A, B, bias, C, M, N, K, lda, ldb, ldc, nH, sAb, sAh, sBb, sBh, sCb, sCh, sbias);
}

template<bool TRANSB, bool RELU, bool RESID, bool CSKIP = false, bool CK = false>
static void gemm_small(const float* A, const float* B, const float* bias, float* C,
                       int M, int N, int K, int lda, int ldb, int ldc,
                       int Z = 1, int nH = 1,
                       long long sAb = 0, long long sAh = 0,
                       long long sBb = 0, long long sBh = 0,
                       long long sCb = 0, long long sCh = 0, long long sbias = 0)
{
    dim3 grid(N / 64, M / 128, Z);
    gemm_tc<128, 64, 32, 32, 32, TRANSB, RELU, RESID, CSKIP, CK><<<grid, 256>>>(
        A, B, bias, C, M, N, K, lda, ldb, ldc, nH, sAb, sAh, sBb, sBh, sCb, sCh, sbias);
}

extern "C" void kernel_launch(void* const* d_in, const int* in_sizes, int n_in,
                              void* d_out, int out_size)
{
    const int*   X      = (const int*)  d_in[0];
    const float* emb    = (const float*)d_in[1];
    const float* pos    = (const float*)d_in[2];
    const float* Wq     = (const float*)d_in[3];
    const float* bq     = (const float*)d_in[4];
    const float* Wk     = (const float*)d_in[5];
    const float* bk     = (const float*)d_in[6];
    const float* Wv     = (const float*)d_in[7];
    const float* bv     = (const float*)d_in[8];
    const float* Wo     = (const float*)d_in[9];
    const float* bo     = (const float*)d_in[10];
    const float* ln1s   = (const float*)d_in[11];
    const float* ln1b   = (const float*)d_in[12];
    const float* ln2s   = (const float*)d_in[13];
    const float* ln2b   = (const float*)d_in[14];
    const float* W1     = (const float*)d_in[15];
    const float* b1     = (const float*)d_in[16];
    const float* W2     = (const float*)d_in[17];
    const float* b2     = (const float*)d_in[18];
    const float* lnfs   = (const float*)d_in[19];
    const float* lnfb   = (const float*)d_in[20];
    const float* headb  = (const float*)d_in[21];
    float* out = (float*)d_out;

    float *x, *xn, *q, *k, *v, *ao, *h1, *sc;
    cudaGetSymbolAddress((void**)&x,  g_x);
    cudaGetSymbolAddress((void**)&xn, g_xn);
    cudaGetSymbolAddress((void**)&q,  g_q);
    cudaGetSymbolAddress((void**)&k,  g_k);
    cudaGetSymbolAddress((void**)&v,  g_v);
    cudaGetSymbolAddress((void**)&ao, g_ao);
    cudaGetSymbolAddress((void**)&h1, g_h1);
    cudaGetSymbolAddress((void**)&sc, g_sc);

    const long long sT = (long long)SEQ * DDIM;          // per-batch stride in [T,768] bufs
    const long long sSS = (long long)SEQ * SEQ;          // per-head stride in scores
    const float attn_scale = 0.125f;                     // 1/sqrt(64)

    // x = emb[X] + pos
    embed_k<<<TTOK, 256>>>(X, emb, pos, x);

    for (int l = 0; l < LNUM; l++) {
        const float* Wq_l = Wq + (long long)l * HNUM * DDIM * DHD;
        const float* Wk_l = Wk + (long long)l * HNUM * DDIM * DHD;
        const float* Wv_l = Wv + (long long)l * HNUM * DDIM * DHD;
        const float* bq_l = bq + (long long)l * HNUM * DHD;
        const float* bk_l = bk + (long long)l * HNUM * DHD;
        const float* bv_l = bv + (long long)l * HNUM * DHD;

        // xn = LN1(x)
        ln_k<<<TTOK, 256>>>(x, ln1s + l * DDIM, ln1b + l * DDIM, xn);

        // q/k/v: per-head GEMM [T,768] @ [768,64]; layout [T, H*DH]
        gemm_small<false, false, false>(xn, Wq_l, bq_l, q, TTOK, DHD, DDIM, DDIM, DHD, DDIM,
                                        HNUM, HNUM, 0, 0, 0, (long long)DDIM * DHD, 0, DHD, DHD);
        gemm_small<false, false, false>(xn, Wk_l, bk_l, k, TTOK, DHD, DDIM, DDIM, DHD, DDIM,
                                        HNUM, HNUM, 0, 0, 0, (long long)DDIM * DHD, 0, DHD, DHD);
        gemm_small<false, false, false>(xn, Wv_l, bv_l, v, TTOK, DHD, DDIM, DDIM, DHD, DDIM,
                                        HNUM, HNUM, 0, 0, 0, (long long)DDIM * DHD, 0, DHD, DHD);

        // scores[b,h] = q[b,h] @ k[b,h]^T   (M=N=1024, K=64); skip masked blocks
        gemm_big<true, false, false, true, false>(q, k, nullptr, sc, SEQ, SEQ, DHD, DDIM, DDIM, SEQ,
                                     BAT * HNUM, HNUM,
                                     sT, DHD, sT, DHD,
                                     (long long)HNUM * sSS, sSS, 0);

        // causal softmax with scale
        softmax_k<<<BAT * HNUM * SEQ, 256>>>(sc, attn_scale);

        // ao[b,h] = attn @ v[b,h]   (M=1024, N=64, K<=m0+128 via causality)
        gemm_small<false, false, false, false, true>(sc, v, nullptr, ao, SEQ, DHD, SEQ, SEQ, DDIM, DDIM,
                                        BAT * HNUM, HNUM,
                                        (long long)HNUM * sSS, sSS,
                                        sT, DHD, sT, DHD, 0);

        // x += ao @ Wo + bo
        gemm_big<false, false, true>(ao, Wo + (long long)l * DDIM * DDIM, bo + l * DDIM, x,
                                     TTOK, DDIM, DDIM, DDIM, DDIM, DDIM);

        // xn = LN2(x)
        ln_k<<<TTOK, 256>>>(x, ln2s + l * DDIM, ln2b + l * DDIM, xn);

        // h1 = relu(xn @ W1 + b1)
        gemm_big<false, true, false>(xn, W1 + (long long)l * DDIM * FDIM, b1 + l * FDIM, h1,
                                     TTOK, FDIM, DDIM, DDIM, FDIM, FDIM);

        // x += h1 @ W2 + b2
        gemm_big<false, false, true>(h1, W2 + (long long)l * FDIM * DDIM, b2 + l * DDIM, x,
                                     TTOK, DDIM, FDIM, FDIM, DDIM, DDIM);
    }

    // xn = LNf(x)
    ln_k<<<TTOK, 256>>>(x, lnfs, lnfb, xn);

    // logits = xn @ emb^T + head_b   (M=2048, N=32000, K=768)
    gemm_big<true, false, false>(xn, emb, headb, out, TTOK, VOC, DDIM, DDIM, DDIM, VOC);
}

// round 4
// speedup vs baseline: 2.1282x; 1.2985x over previous
#include <cuda_runtime.h>
#include <cuda_bf16.h>
#include <mma.h>
#include <cstdint>

using namespace nvcuda;
typedef __nv_bfloat16 bf16;

#define LNUM 6
#define HNUM 12
#define DDIM 768
#define DHD  64
#define FDIM 3072
#define VOC  32000
#define SEQ  1024
#define BAT  2
#define TTOK (BAT*SEQ)
#define QKVN (3*DDIM)
#define EPS  1e-5f

// ---------------- scratch (static device globals; no allocation) ----------------
__device__ float g_x [TTOK*DDIM];
__device__ float g_sc[(long long)BAT*HNUM*SEQ*SEQ];
__device__ bf16 g_xnh[TTOK*DDIM],  g_xnl[TTOK*DDIM];
__device__ bf16 g_qkvh[(long long)TTOK*QKVN], g_qkvl[(long long)TTOK*QKVN];
__device__ bf16 g_aoh[TTOK*DDIM],  g_aol[TTOK*DDIM];
__device__ bf16 g_h1h[(long long)TTOK*FDIM], g_h1l[(long long)TTOK*FDIM];
__device__ bf16 g_pph[(long long)BAT*HNUM*SEQ*SEQ], g_ppl[(long long)BAT*HNUM*SEQ*SEQ];
// pre-split weights
__device__ bf16 g_wqkvh[(long long)LNUM*DDIM*QKVN], g_wqkvl[(long long)LNUM*DDIM*QKVN];
__device__ float g_bqkv[LNUM*QKVN];
__device__ bf16 g_woh[(long long)LNUM*DDIM*DDIM],  g_wol[(long long)LNUM*DDIM*DDIM];
__device__ bf16 g_w1h[(long long)LNUM*DDIM*FDIM],  g_w1l[(long long)LNUM*DDIM*FDIM];
__device__ bf16 g_w2h[(long long)LNUM*FDIM*DDIM],  g_w2l[(long long)LNUM*FDIM*DDIM];
__device__ bf16 g_embh[(long long)VOC*DDIM],       g_embl[(long long)VOC*DDIM];

// ---------------- helpers ----------------
__device__ __forceinline__ void split2(float v, bf16& h, bf16& l) {
    h = __float2bfloat16(v);
    l = __float2bfloat16(v - __bfloat162float(h));
}
__device__ __forceinline__ void cp16(bf16* dst, const bf16* src) {
    unsigned int d = (unsigned int)__cvta_generic_to_shared(dst);
    asm volatile("cp.async.cg.shared.global [%0], [%1], 16;" :: "r"(d), "l"(src));
}
__device__ __forceinline__ void cp_commit() { asm volatile("cp.async.commit_group;"); }
template<int N> __device__ __forceinline__ void cp_wait() {
    asm volatile("cp.async.wait_group %0;" :: "n"(N));
}
__device__ __forceinline__ float warp_sum(float v) {
    #pragma unroll
    for (int o = 16; o; o >>= 1) v += __shfl_xor_sync(0xffffffffu, v, o);
    return v;
}

// ---------------- weight pre-split kernels ----------------
// [L,H,D,DH] -> [L, D, 3*D] slab at column offset coloff, scaled
__global__ void split_qkv_k(const float* __restrict__ src, bf16* __restrict__ hi,
                            bf16* __restrict__ lo, int coloff, float scale)
{
    long long idx = (long long)blockIdx.x * 256 + threadIdx.x;   // L*H*D*DH total
    int kk = (int)(idx & (DHD - 1));
    long long t = idx >> 6;
    int d = (int)(t % DDIM); t /= DDIM;
    int h = (int)(t % HNUM);
    int l = (int)(t / HNUM);
    long long dst = ((long long)l * DDIM + d) * QKVN + coloff + h * DHD + kk;
    float v = src[idx] * scale;
    bf16 hh, ll; split2(v, hh, ll);
    hi[dst] = hh; lo[dst] = ll;
}

__global__ void bias_qkv_k(const float* __restrict__ bq, const float* __restrict__ bk,
                           const float* __restrict__ bv)
{
    int i = blockIdx.x * 256 + threadIdx.x;   // L*3*D total
    int col = i % QKVN, l = i / QKVN;
    float v;
    if (col < DDIM)            v = bq[l * DDIM + col] * 0.125f;
    else if (col < 2 * DDIM)   v = bk[l * DDIM + col - DDIM];
    else                       v = bv[l * DDIM + col - 2 * DDIM];
    g_bqkv[i] = v;
}

__global__ void split_plain_k(const float4* __restrict__ src, bf16* __restrict__ hi,
                              bf16* __restrict__ lo, long long n4)
{
    long long i = (long long)blockIdx.x * 256 + threadIdx.x;
    if (i >= n4) return;
    float4 v = src[i];
    bf16 h, l;
    __nv_bfloat162* h2 = (__nv_bfloat162*)hi;
    __nv_bfloat162* l2 = (__nv_bfloat162*)lo;
    __nv_bfloat162 ha, hb, la, lb;
    split2(v.x, h, l); ha.x = h; la.x = l;
    split2(v.y, h, l); ha.y = h; la.y = l;
    split2(v.z, h, l); hb.x = h; lb.x = l;
    split2(v.w, h, l); hb.y = h; lb.y = l;
    h2[2*i] = ha; h2[2*i+1] = hb;
    l2[2*i] = la; l2[2*i+1] = lb;
}

// ---------------- embedding ----------------
__global__ void embed_k(const int* __restrict__ X, const float* __restrict__ emb,
                        const float* __restrict__ pos, float* __restrict__ x)
{
    int t = blockIdx.x;
    int tok = X[t];
    int s = t % SEQ;
    const float* er = emb + (long long)tok * DDIM;
    const float* pr = pos + (long long)s * DDIM;
    float* xr = x + (long long)t * DDIM;
    for (int d = threadIdx.x; d < DDIM; d += blockDim.x)
        xr[d] = er[d] + pr[d];
}

// ---------------- layernorm -> split bf16 output ----------------
__global__ void ln_k(const float* __restrict__ x, const float* __restrict__ g,
                     const float* __restrict__ b, bf16* __restrict__ yh,
                     bf16* __restrict__ yl)
{
    int row = blockIdx.x;
    const float* xr = x + (long long)row * DDIM;
    bf16* yhr = yh + (long long)row * DDIM;
    bf16* ylr = yl + (long long)row * DDIM;
    int tid = threadIdx.x;

    float sum = 0.f, sq = 0.f;
    for (int i = tid; i < DDIM; i += 256) {
        float v = xr[i];
        sum += v; sq += v * v;
    }
    __shared__ float shs[8], shq[8];
    float s1 = warp_sum(sum), s2 = warp_sum(sq);
    int wid = tid >> 5, lane = tid & 31;
    if (lane == 0) { shs[wid] = s1; shq[wid] = s2; }
    __syncthreads();
    float ts = 0.f, tq = 0.f;
    #pragma unroll
    for (int w = 0; w < 8; w++) { ts += shs[w]; tq += shq[w]; }
    float mu = ts * (1.0f / DDIM);
    float var = tq * (1.0f / DDIM) - mu * mu;
    float r = rsqrtf(var + EPS);
    for (int i = tid; i < DDIM; i += 256) {
        float o = (xr[i] - mu) * r * g[i] + b[i];
        bf16 h, l; split2(o, h, l);
        yhr[i] = h; ylr[i] = l;
    }
}

// ---------------- causal softmax (scores pre-scaled), split bf16 output ----------------
__global__ void softmax_k(const float* __restrict__ sc, bf16* __restrict__ ph,
                          bf16* __restrict__ pl)
{
    long long row = blockIdx.x;
    int s = (int)(row % SEQ);
    const float* p = sc + row * (long long)SEQ;
    bf16* oh = ph + row * (long long)SEQ;
    bf16* ol = pl + row * (long long)SEQ;
    int n = s + 1;
    int tid = threadIdx.x;

    float lv[4];
    float mx = -1e30f;
    #pragma unroll
    for (int it = 0; it < 4; it++) {
        int i = tid + it * 256;
        if (i < n) { lv[it] = p[i]; mx = fmaxf(mx, lv[it]); }
    }
    __shared__ float sh[8];
    #pragma unroll
    for (int o = 16; o; o >>= 1) mx = fmaxf(mx, __shfl_xor_sync(0xffffffffu, mx, o));
    int wid = tid >> 5, lane = tid & 31;
    if (lane == 0) sh[wid] = mx;
    __syncthreads();
    float gmx = -1e30f;
    #pragma unroll
    for (int w = 0; w < 8; w++) gmx = fmaxf(gmx, sh[w]);
    __syncthreads();

    float sum = 0.f;
    #pragma unroll
    for (int it = 0; it < 4; it++) {
        int i = tid + it * 256;
        if (i < n) { float e = __expf(lv[it] - gmx); lv[it] = e; sum += e; }
    }
    float s1 = warp_sum(sum);
    if (lane == 0) sh[wid] = s1;
    __syncthreads();
    float tot = 0.f;
    #pragma unroll
    for (int w = 0; w < 8; w++) tot += sh[w];
    float inv = 1.0f / tot;

    bf16 z = __float2bfloat16(0.f);
    #pragma unroll
    for (int it = 0; it < 4; it++) {
        int i = tid + it * 256;
        if (i < n) { bf16 h, l; split2(lv[it] * inv, h, l); oh[i] = h; ol[i] = l; }
    }
    for (int i = n + tid; i < SEQ; i += 256) { oh[i] = z; ol[i] = z; }
}

// ---------------- bf16-split tensor-core GEMM, cp.async double-buffered ------------
// C = A*B (+bias) (+C_old) (relu); A,B given as pre-split hi/lo bf16.
// TRANSB: B stored [N,K] (use col_major fragments).
// CSKIP: skip fully-masked causal blocks; CKLIM: K limited to m0+BM.
// OSPLIT: write hi/lo bf16 outputs, else fp32.
template<int BM, int BN, int BK, int WM, int WN,
         bool TRANSB, bool RELU, bool RESID, bool CSKIP, bool CKLIM, bool OSPLIT>
__global__ void __launch_bounds__(256) gemm_tc(
    const bf16* __restrict__ Ahig, const bf16* __restrict__ Alog,
    const bf16* __restrict__ Bhig, const bf16* __restrict__ Blog,
    const float* __restrict__ biasg,
    float* __restrict__ Cg, bf16* __restrict__ Chig, bf16* __restrict__ Clog,
    int K, int lda, int ldb, int ldc, int nH,
    long long sAb, long long sAh, long long sBb, long long sBh,
    long long sCb, long long sCh)
{
    constexpr int LDA = BK + 8;
    constexpr int BROWS = TRANSB ? BN : BK;
    constexpr int LDB = TRANSB ? (BK + 8) : (BN + 8);
    constexpr int A_EL = BM * LDA;
    constexpr int B_EL = BROWS * LDB;
    constexpr int MI = WM / 16, NI = WN / 16;
    static_assert((BM / WM) * (BN / WN) == 8, "8 warps");

    const int m0 = blockIdx.y * BM;
    const int n0 = blockIdx.x * BN;
    if (CSKIP && n0 >= m0 + BM) return;

    const int z = blockIdx.z;
    const int bz = z / nH, hz = z - bz * nH;
    const bf16* Ahi = Ahig + bz * sAb + hz * sAh;
    const bf16* Alo = Alog + bz * sAb + hz * sAh;
    const bf16* Bhi = Bhig + bz * sBb + hz * sBh;
    const bf16* Blo = Blog + bz * sBb + hz * sBh;
    const long long coff = bz * sCb + hz * sCh;

    extern __shared__ char smraw[];
    bf16* sAhi = (bf16*)smraw;
    bf16* sAlo = sAhi + 2 * A_EL;
    bf16* sBhi = sAlo + 2 * A_EL;
    bf16* sBlo = sBhi + 2 * B_EL;
    float* stg = (float*)(sBlo + 2 * B_EL);

    const int tid = threadIdx.x;
    const int w = tid >> 5, lane = tid & 31;
    const int warp_m = (w / (BN / WN)) * WM;
    const int warp_n = (w % (BN / WN)) * WN;

    wmma::fragment<wmma::accumulator, 16, 16, 16, float> acc[MI][NI];
    #pragma unroll
    for (int i = 0; i < MI; i++)
        #pragma unroll
        for (int j = 0; j < NI; j++) wmma::fill_fragment(acc[i][j], 0.f);

    const int Kend = CKLIM ? ((m0 + BM < K) ? (m0 + BM) : K) : K;
    const int nk = Kend / BK;

    auto load_stage = [&](int kt, int s) {
        const int k0 = kt * BK;
        constexpr int CA = BM * BK / 8;
        #pragma unroll
        for (int it = 0; it < CA / 256; it++) {
            int v = tid + it * 256;
            int row = v / (BK / 8), c = v % (BK / 8);
            long long g = (long long)(m0 + row) * lda + k0 + c * 8;
            int sm = s * A_EL + row * LDA + c * 8;
            cp16(sAhi + sm, Ahi + g);
            cp16(sAlo + sm, Alo + g);
        }
        constexpr int CB = BK * BN / 8;
        #pragma unroll
        for (int it = 0; it < CB / 256; it++) {
            int v = tid + it * 256;
            if (!TRANSB) {
                int row = v / (BN / 8), c = v % (BN / 8);
                long long g = (long long)(k0 + row) * ldb + n0 + c * 8;
                int sm = s * B_EL + row * LDB + c * 8;
                cp16(sBhi + sm, Bhi + g);
                cp16(sBlo + sm, Blo + g);
            } else {
                int row = v / (BK / 8), c = v % (BK / 8);
                long long g = (long long)(n0 + row) * ldb + k0 + c * 8;
                int sm = s * B_EL + row * LDB + c * 8;
                cp16(sBhi + sm, Bhi + g);
                cp16(sBlo + sm, Blo + g);
            }
        }
    };

    load_stage(0, 0);
    cp_commit();

    for (int kt = 0; kt < nk; kt++) {
        const int s = kt & 1;
        if (kt + 1 < nk) { load_stage(kt + 1, s ^ 1); cp_commit(); cp_wait<1>(); }
        else             cp_wait<0>();
        __syncthreads();

        #pragma unroll
        for (int kk = 0; kk < BK / 16; kk++) {
            wmma::fragment<wmma::matrix_a, 16, 16, 16, bf16, wmma::row_major> ahi[MI], alo[MI];
            #pragma unroll
            for (int i = 0; i < MI; i++) {
                int off = s * A_EL + (warp_m + i * 16) * LDA + kk * 16;
                wmma::load_matrix_sync(ahi[i], sAhi + off, LDA);
                wmma::load_matrix_sync(alo[i], sAlo + off, LDA);
            }
            #pragma unroll
            for (int j = 0; j < NI; j++) {
                if constexpr (TRANSB) {
                    wmma::fragment<wmma::matrix_b, 16, 16, 16, bf16, wmma::col_major> bhi, blo;
                    int off = s * B_EL + (warp_n + j * 16) * LDB + kk * 16;
                    wmma::load_matrix_sync(bhi, sBhi + off, LDB);
                    wmma::load_matrix_sync(blo, sBlo + off, LDB);
                    #pragma unroll
                    for (int i = 0; i < MI; i++) {
                        wmma::mma_sync(acc[i][j], ahi[i], bhi, acc[i][j]);
                        wmma::mma_sync(acc[i][j], ahi[i], blo, acc[i][j]);
                        wmma::mma_sync(acc[i][j], alo[i], bhi, acc[i][j]);
                    }
                } else {
                    wmma::fragment<wmma::matrix_b, 16, 16, 16, bf16, wmma::row_major> bhi, blo;
                    int off = s * B_EL + (kk * 16) * LDB + warp_n + j * 16;
                    wmma::load_matrix_sync(bhi, sBhi + off, LDB);
                    wmma::load_matrix_sync(blo, sBlo + off, LDB);
                    #pragma unroll
                    for (int i = 0; i < MI; i++) {
                        wmma::mma_sync(acc[i][j], ahi[i], bhi, acc[i][j]);
                        wmma::mma_sync(acc[i][j], ahi[i], blo, acc[i][j]);
                        wmma::mma_sync(acc[i][j], alo[i], bhi, acc[i][j]);
                    }
                }
            }
        }
        __syncthreads();
    }

    // ---- epilogue via per-warp smem staging ----
    #pragma unroll
    for (int i = 0; i < MI; i++) {
        #pragma unroll
        for (int j = 0; j < NI; j++) {
            wmma::store_matrix_sync(stg + w * 256, acc[i][j], 16, wmma::mem_row_major);
            __syncwarp();
            #pragma unroll
            for (int e = 0; e < 8; e++) {
                int idx = lane + 32 * e;
                int r = idx >> 4, c = idx & 15;
                int m = m0 + warp_m + i * 16 + r;
                int n = n0 + warp_n + j * 16 + c;
                long long cidx = (long long)m * ldc + n + coff;
                float v = stg[w * 256 + idx];
                if (biasg) v += __ldg(biasg + n);
                if (RESID) v += Cg[cidx];
                if (RELU)  v = fmaxf(v, 0.f);
                if (OSPLIT) { bf16 h, l; split2(v, h, l); Chig[cidx] = h; Clog[cidx] = l; }
                else        Cg[cidx] = v;
            }
            __syncwarp();
        }
    }
}

// ---------------- host launcher ----------------
template<int BM, int BN, int BK, int WM, int WN,
         bool TRANSB, bool RELU, bool RESID, bool CSKIP, bool CKLIM, bool OSPLIT>
static void run_gemm(const bf16* Ahi, const bf16* Alo, const bf16* Bhi, const bf16* Blo,
                     const float* bias, float* C, bf16* Chi, bf16* Clo,
                     int M, int N, int K, int lda, int ldb, int ldc,
                     int Z = 1, int nH = 1,
                     long long sAb = 0, long long sAh = 0,
                     long long sBb = 0, long long sBh = 0,
                     long long sCb = 0, long long sCh = 0)
{
    constexpr int LDA = BK + 8;
    constexpr int BROWS = TRANSB ? BN : BK;
    constexpr int LDB = TRANSB ? (BK + 8) : (BN + 8);
    constexpr size_t SB = (size_t)8 * BM * LDA + (size_t)8 * BROWS * LDB + 8192;
    auto fn = gemm_tc<BM, BN, BK, WM, WN, TRANSB, RELU, RESID, CSKIP, CKLIM, OSPLIT>;
    cudaFuncSetAttribute(fn, cudaFuncAttributeMaxDynamicSharedMemorySize, (int)SB);
    dim3 grid(N / BN, M / BM, Z);
    fn<<<grid, 256, SB>>>(Ahi, Alo, Bhi, Blo, bias, C, Chi, Clo,
                          K, lda, ldb, ldc, nH, sAb, sAh, sBb, sBh, sCb, sCh);
}

extern "C" void kernel_launch(void* const* d_in, const int* in_sizes, int n_in,
                              void* d_out, int out_size)
{
    const int*   X      = (const int*)  d_in[0];
    const float* emb    = (const float*)d_in[1];
    const float* pos    = (const float*)d_in[2];
    const float* Wq     = (const float*)d_in[3];
    const float* bq     = (const float*)d_in[4];
    const float* Wk     = (const float*)d_in[5];
    const float* bk     = (const float*)d_in[6];
    const float* Wv     = (const float*)d_in[7];
    const float* bv     = (const float*)d_in[8];
    const float* Wo     = (const float*)d_in[9];
    const float* bo     = (const float*)d_in[10];
    const float* ln1s   = (const float*)d_in[11];
    const float* ln1b   = (const float*)d_in[12];
    const float* ln2s   = (const float*)d_in[13];
    const float* ln2b   = (const float*)d_in[14];
    const float* W1     = (const float*)d_in[15];
    const float* b1     = (const float*)d_in[16];
    const float* W2     = (const float*)d_in[17];
    const float* b2     = (const float*)d_in[18];
    const float* lnfs   = (const float*)d_in[19];
    const float* lnfb   = (const float*)d_in[20];
    const float* headb  = (const float*)d_in[21];
    float* out = (float*)d_out;

    float *x, *sc, *bqkv;
    bf16 *xnh, *xnl, *qkvh, *qkvl, *aoh, *aol, *h1h, *h1l, *pph, *ppl;
    bf16 *wqkvh, *wqkvl, *woh, *wol, *w1h, *w1l, *w2h, *w2l, *embh, *embl;
    cudaGetSymbolAddress((void**)&x,     g_x);
    cudaGetSymbolAddress((void**)&sc,    g_sc);
    cudaGetSymbolAddress((void**)&xnh,   g_xnh);
    cudaGetSymbolAddress((void**)&xnl,   g_xnl);
    cudaGetSymbolAddress((void**)&qkvh,  g_qkvh);
    cudaGetSymbolAddress((void**)&qkvl,  g_qkvl);
    cudaGetSymbolAddress((void**)&aoh,   g_aoh);
    cudaGetSymbolAddress((void**)&aol,   g_aol);
    cudaGetSymbolAddress((void**)&h1h,   g_h1h);
    cudaGetSymbolAddress((void**)&h1l,   g_h1l);
    cudaGetSymbolAddress((void**)&pph,   g_pph);
    cudaGetSymbolAddress((void**)&ppl,   g_ppl);
    cudaGetSymbolAddress((void**)&wqkvh, g_wqkvh);
    cudaGetSymbolAddress((void**)&wqkvl, g_wqkvl);
    cudaGetSymbolAddress((void**)&bqkv,  g_bqkv);
    cudaGetSymbolAddress((void**)&woh,   g_woh);
    cudaGetSymbolAddress((void**)&wol,   g_wol);
    cudaGetSymbolAddress((void**)&w1h,   g_w1h);
    cudaGetSymbolAddress((void**)&w1l,   g_w1l);
    cudaGetSymbolAddress((void**)&w2h,   g_w2h);
    cudaGetSymbolAddress((void**)&w2l,   g_w2l);
    cudaGetSymbolAddress((void**)&embh,  g_embh);
    cudaGetSymbolAddress((void**)&embl,  g_embl);

    // ---- weight pre-split (once per call) ----
    split_qkv_k<<<13824, 256>>>(Wq, wqkvh, wqkvl, 0,        0.125f);  // fold 1/sqrt(64)
    split_qkv_k<<<13824, 256>>>(Wk, wqkvh, wqkvl, DDIM,     1.0f);
    split_qkv_k<<<13824, 256>>>(Wv, wqkvh, wqkvl, 2 * DDIM, 1.0f);
    bias_qkv_k<<<54, 256>>>(bq, bk, bv);
    split_plain_k<<< 3456, 256>>>((const float4*)Wo,  woh,  wol,  (long long)LNUM*DDIM*DDIM/4);
    split_plain_k<<<13824, 256>>>((const float4*)W1,  w1h,  w1l,  (long long)LNUM*DDIM*FDIM/4);
    split_plain_k<<<13824, 256>>>((const float4*)W2,  w2h,  w2l,  (long long)LNUM*FDIM*DDIM/4);
    split_plain_k<<<24000, 256>>>((const float4*)emb, embh, embl, (long long)VOC*DDIM/4);

    const long long sTq = (long long)SEQ * QKVN;   // per-batch stride in qkv buffer
    const long long sT  = (long long)SEQ * DDIM;
    const long long sSS = (long long)SEQ * SEQ;

    // x = emb[X] + pos
    embed_k<<<TTOK, 256>>>(X, emb, pos, x);

    for (int l = 0; l < LNUM; l++) {
        // xn = LN1(x) (split)
        ln_k<<<TTOK, 256>>>(x, ln1s + l * DDIM, ln1b + l * DDIM, xnh, xnl);

        // fused qkv = xn @ Wqkv + bqkv  -> split [T, 2304]
        run_gemm<128, 128, 32, 32, 64, false, false, false, false, false, true>(
            xnh, xnl, wqkvh + (long long)l * DDIM * QKVN, wqkvl + (long long)l * DDIM * QKVN,
            bqkv + l * QKVN, nullptr, qkvh, qkvl,
            TTOK, QKVN, DDIM, DDIM, QKVN, QKVN);

        // scores[b,h] = q @ k^T (scale already folded into Wq); causal skip
        run_gemm<128, 128, 32, 32, 64, true, false, false, true, false, false>(
            qkvh, qkvl, qkvh + DDIM, qkvl + DDIM, nullptr, sc, nullptr, nullptr,
            SEQ, SEQ, DHD, QKVN, QKVN, SEQ,
            BAT * HNUM, HNUM, sTq, DHD, sTq, DHD,
            (long long)HNUM * sSS, sSS);

        // causal softmax -> split probs
        softmax_k<<<BAT * HNUM * SEQ, 256>>>(sc, pph, ppl);

        // ao[b,h] = P @ v (K limited by causality) -> split [T, 768]
        run_gemm<128, 64, 32, 32, 32, false, false, false, false, true, true>(
            pph, ppl, qkvh + 2 * DDIM, qkvl + 2 * DDIM, nullptr, nullptr, aoh, aol,
            SEQ, DHD, SEQ, SEQ, QKVN, DDIM,
            BAT * HNUM, HNUM, (long long)HNUM * sSS, sSS,
            sTq, DHD, sT, DHD);

        // x += ao @ Wo + bo
        run_gemm<128, 64, 32, 32, 32, false, false, true, false, false, false>(
            aoh, aol, woh + (long long)l * DDIM * DDIM, wol + (long long)l * DDIM * DDIM,
            bo + l * DDIM, x, nullptr, nullptr,
            TTOK, DDIM, DDIM, DDIM, DDIM, DDIM);

        // xn = LN2(x)
        ln_k<<<TTOK, 256>>>(x, ln2s + l * DDIM, ln2b + l * DDIM, xnh, xnl);

        // h1 = relu(xn @ W1 + b1) -> split
        run_gemm<128, 128, 32, 32, 64, false, true, false, false, false, true>(
            xnh, xnl, w1h + (long long)l * DDIM * FDIM, w1l + (long long)l * DDIM * FDIM,
            b1 + l * FDIM, nullptr, h1h, h1l,
            TTOK, FDIM, DDIM, DDIM, FDIM, FDIM);

        // x += h1 @ W2 + b2
        run_gemm<128, 64, 32, 32, 32, false, false, true, false, false, false>(
            h1h, h1l, w2h + (long long)l * FDIM * DDIM, w2l + (long long)l * FDIM * DDIM,
            b2 + l * DDIM, x, nullptr, nullptr,
            TTOK, DDIM, FDIM, FDIM, DDIM, DDIM);
    }

    // xn = LNf(x)
    ln_k<<<TTOK, 256>>>(x, lnfs, lnfb, xnh, xnl);

    // logits = xn @ emb^T + head_b
    run_gemm<128, 128, 32, 32, 64, true, false, false, false, false, false>(
        xnh, xnl, embh, embl, headb, out, nullptr, nullptr,
        TTOK, VOC, DDIM, DDIM, DDIM, VOC);
}